// round 1
// baseline (speedup 1.0000x reference)
#include <cuda_runtime.h>
#include <cstdint>

// TokenBladeBank: FNV-1a 4-gram hash -> gather from 8 blade banks.
// token_window: (8, 8192, 4) int32 OR int64 (runtime-detected)
// bank:         (8, 500000, 16) float32
// out:          (8, 8192, 8, 16) float32  ->  out[pos*128 + blade*16 + d]

#define TBB_N_SLOTS  500000u
#define TBB_N_BLADES 8
#define TBB_D_STATE  16
#define TBB_FNV_OFFSET 2166136261u
#define TBB_FNV_PRIME  16777619u

// 1 = tokens are int32 (read every u32 word), 2 = tokens are int64 (read every
// other u32 word, little-endian low half).
__device__ int g_tok_stride;

// Little-endian int64 layout => every odd u32 word is the (zero) high half of a
// token < 50257. For int32 layout, odd words are random tokens; P(all 32
// checked words are zero) ~ 50257^-32 ~ 0.
__global__ void tbb_detect_kernel(const unsigned* __restrict__ tw)
{
    unsigned acc = 0;
    #pragma unroll
    for (int i = 1; i < 64; i += 2) acc |= tw[i];
    g_tok_stride = (acc == 0) ? 2 : 1;
}

__global__ void __launch_bounds__(256)
tbb_gather_kernel(const unsigned* __restrict__ tw,
                  const float4*  __restrict__ bank,
                  float4*        __restrict__ out,
                  int n_pos)
{
    const int t    = blockIdx.x * blockDim.x + threadIdx.x;
    const int pos  = t >> 5;
    if (pos >= n_pos) return;
    const int lane = t & 31;

    const int stride = g_tok_stride;  // broadcast L2 load, uniform

    // FNV-1a over the 4-gram (low 32 bits of each token; tokens < 50257 so
    // low word is exact for both int32 and int64 inputs).
    unsigned h = TBB_FNV_OFFSET;
    #pragma unroll
    for (int i = 0; i < 4; i++) {
        unsigned tok = __ldg(&tw[(pos * 4 + i) * stride]);
        h = (h ^ tok) * TBB_FNV_PRIME;
    }
    const unsigned addr = h % TBB_N_SLOTS;

    // Warp = one position. lane -> (blade, quarter-row).
    const unsigned blade = (unsigned)lane >> 2;   // 0..7
    const unsigned q     = (unsigned)lane & 3;    // 0..3 (float4 within 16 floats)

    // bank viewed as float4[]: row (blade, addr) starts at (blade*N_SLOTS+addr)*4
    const size_t bidx = ((size_t)blade * TBB_N_SLOTS + (size_t)addr) * 4 + q;
    float4 v = __ldg(&bank[bidx]);

    // out viewed as float4[]: position owns 32 contiguous float4 (512 B),
    // ordered blade-major then quarter — exactly lane order. Fully coalesced.
    out[(size_t)pos * 32 + (size_t)lane] = v;
}

extern "C" void kernel_launch(void* const* d_in, const int* in_sizes, int n_in,
                              void* d_out, int out_size)
{
    const unsigned* tw   = (const unsigned*)d_in[0];   // token_window (int32/int64 raw words)
    const float4*   bank = (const float4*)d_in[1];     // bank fp32 rows of 16
    float4*         out  = (float4*)d_out;

    const int n_pos = in_sizes[0] / 4;                 // 8*8192 = 65536 positions

    tbb_detect_kernel<<<1, 1>>>(tw);

    const int threads = 256;
    const int total   = n_pos * 32;                    // one warp (32 lanes) per position
    const int blocks  = (total + threads - 1) / threads;
    tbb_gather_kernel<<<blocks, threads>>>(tw, bank, out, n_pos);
}

// round 2
// speedup vs baseline: 1.2909x; 1.2909x over previous
#include <cuda_runtime.h>
#include <cstdint>

// TokenBladeBank: FNV-1a 4-gram hash -> gather from 8 blade banks.
// token_window: (8, 8192, 4) int32 OR int64 (runtime-detected)
// bank:         (8, 500000, 16) float32
// out:          (8, 8192, 8, 16) float32  ->  out[pos*128 + blade*16 + d]

#define TBB_N_SLOTS   500000u
#define TBB_FNV_OFFSET 2166136261u
#define TBB_FNV_PRIME  16777619u
#define TBB_POS_PER_WARP 4

// 1 = tokens are int32 words, 2 = tokens are int64 (read LE low half).
__device__ int g_tok_stride;

// Little-endian int64 layout => every odd u32 word is a zero high half
// (tokens < 50257). For int32 layout odd words are random tokens;
// P(all 32 checked odd words == 0) ~ 50257^-32 ~ 0.
__global__ void tbb_detect_kernel(const unsigned* __restrict__ tw)
{
    unsigned acc = 0;
    #pragma unroll
    for (int i = 1; i < 64; i += 2) acc |= tw[i];
    g_tok_stride = (acc == 0) ? 2 : 1;
}

__device__ __forceinline__ unsigned tbb_fnv4(unsigned a, unsigned b,
                                             unsigned c, unsigned d)
{
    unsigned h = TBB_FNV_OFFSET;
    h = (h ^ a) * TBB_FNV_PRIME;
    h = (h ^ b) * TBB_FNV_PRIME;
    h = (h ^ c) * TBB_FNV_PRIME;
    h = (h ^ d) * TBB_FNV_PRIME;
    return h % TBB_N_SLOTS;
}

__global__ void __launch_bounds__(256)
tbb_gather_kernel(const unsigned* __restrict__ tw,
                  const float4*  __restrict__ bank,
                  float4*        __restrict__ out,
                  int n_pos)
{
    const int t    = blockIdx.x * blockDim.x + threadIdx.x;
    const int warp = t >> 5;
    const int lane = t & 31;
    const int pos0 = warp * TBB_POS_PER_WARP;
    if (pos0 >= n_pos) return;

    const int stride = g_tok_stride;             // uniform broadcast load
    const unsigned blade = (unsigned)lane >> 2;  // 0..7
    const unsigned q     = (unsigned)lane & 3;   // float4 within the 16-fp row

    const uint4* tw4 = (const uint4*)tw;

    unsigned addr[TBB_POS_PER_WARP];
    if (stride == 1) {
        // int32 layout: one uint4 per 4-gram; 4 independent LDG.128, broadcast
        uint4 tk[TBB_POS_PER_WARP];
        #pragma unroll
        for (int p = 0; p < TBB_POS_PER_WARP; p++)
            tk[p] = __ldg(&tw4[pos0 + p]);
        #pragma unroll
        for (int p = 0; p < TBB_POS_PER_WARP; p++)
            addr[p] = tbb_fnv4(tk[p].x, tk[p].y, tk[p].z, tk[p].w);
    } else {
        // int64 layout: 4-gram spans 32 B = two uint4; take low words (.x,.z)
        uint4 ta[TBB_POS_PER_WARP], tb[TBB_POS_PER_WARP];
        #pragma unroll
        for (int p = 0; p < TBB_POS_PER_WARP; p++) {
            ta[p] = __ldg(&tw4[(size_t)(pos0 + p) * 2]);
            tb[p] = __ldg(&tw4[(size_t)(pos0 + p) * 2 + 1]);
        }
        #pragma unroll
        for (int p = 0; p < TBB_POS_PER_WARP; p++)
            addr[p] = tbb_fnv4(ta[p].x, ta[p].z, tb[p].x, tb[p].z);
    }

    // 4 independent random gathers, issued back-to-back (MLP=4).
    float4 v[TBB_POS_PER_WARP];
    #pragma unroll
    for (int p = 0; p < TBB_POS_PER_WARP; p++) {
        const size_t bidx =
            ((size_t)blade * TBB_N_SLOTS + (size_t)addr[p]) * 4 + q;
        v[p] = __ldg(&bank[bidx]);
    }

    // 4 coalesced 512 B stores -> 2 KB contiguous per warp.
    #pragma unroll
    for (int p = 0; p < TBB_POS_PER_WARP; p++)
        out[(size_t)(pos0 + p) * 32 + lane] = v[p];
}

extern "C" void kernel_launch(void* const* d_in, const int* in_sizes, int n_in,
                              void* d_out, int out_size)
{
    const unsigned* tw   = (const unsigned*)d_in[0];
    const float4*   bank = (const float4*)d_in[1];
    float4*         out  = (float4*)d_out;

    const int n_pos = in_sizes[0] / 4;           // 65536 positions

    tbb_detect_kernel<<<1, 1>>>(tw);

    const int threads = 256;
    const int warps   = (n_pos + TBB_POS_PER_WARP - 1) / TBB_POS_PER_WARP;
    const int blocks  = (warps * 32 + threads - 1) / threads;
    tbb_gather_kernel<<<blocks, threads>>>(tw, bank, out, n_pos);
}